// round 1
// baseline (speedup 1.0000x reference)
#include <cuda_runtime.h>
#include <cuda_bf16.h>
#include <math.h>

#define N_NODES   8192
#define C_IN      256
#define C_OUT     128
#define NEG_SLOPE 0.2f
#define MAX_DEG   128

// -------- scratch (no allocations allowed; __device__ globals) --------
__device__ float g_h[N_NODES * C_OUT];      // 4 MB, h = x @ W
__device__ float g_asrc[N_NODES];
__device__ float g_adst[N_NODES];
__device__ int   g_cnt[N_NODES];            // per-column degree (excl. self)
__device__ int   g_list[N_NODES * MAX_DEG]; // 4 MB, CSC row lists

// ---------------------------------------------------------------------
// Kernel 0: reset counters (graph replays must be idempotent)
// ---------------------------------------------------------------------
__global__ void zero_cnt_kernel() {
    int t = blockIdx.x * blockDim.x + threadIdx.x;
    if (t < N_NODES) g_cnt[t] = 0;
}

// ---------------------------------------------------------------------
// Kernel 1: h = x @ W   (8192x256 @ 256x128, fp32)
// BM=64 rows per block, BN=128 (full C_OUT), BK=16.
// 256 threads, each computes an 8x4 micro-tile.
// ---------------------------------------------------------------------
#define BM 64
#define BK 16
__global__ __launch_bounds__(256) void gemm_h_kernel(
    const float* __restrict__ x, const float* __restrict__ W) {
    __shared__ float xs[BK][BM];
    __shared__ float ws[BK][C_OUT];

    int tid  = threadIdx.x;
    int row0 = blockIdx.x * BM;
    int tx = tid & 31;   // col group: c = tx*4
    int ty = tid >> 5;   // row group: r0 = ty*8

    float acc[8][4];
#pragma unroll
    for (int r = 0; r < 8; r++)
#pragma unroll
        for (int c = 0; c < 4; c++) acc[r][c] = 0.0f;

    for (int k0 = 0; k0 < C_IN; k0 += BK) {
        // load x tile: 64 rows x 16 k  (each thread: one float4)
        {
            int r  = tid >> 2;          // 0..63
            int kk = (tid & 3) * 4;     // 0,4,8,12
            float4 v = *reinterpret_cast<const float4*>(
                &x[(row0 + r) * C_IN + k0 + kk]);
            xs[kk + 0][r] = v.x; xs[kk + 1][r] = v.y;
            xs[kk + 2][r] = v.z; xs[kk + 3][r] = v.w;
        }
        // load W tile: 16 k x 128 c (each thread: two float4)
        {
            int kk = tid >> 5;              // 0..7
            int c  = (tid & 31) * 4;
            *reinterpret_cast<float4*>(&ws[kk][c]) =
                *reinterpret_cast<const float4*>(&W[(k0 + kk) * C_OUT + c]);
            *reinterpret_cast<float4*>(&ws[kk + 8][c]) =
                *reinterpret_cast<const float4*>(&W[(k0 + kk + 8) * C_OUT + c]);
        }
        __syncthreads();
#pragma unroll
        for (int kk = 0; kk < BK; kk++) {
            float4 b = *reinterpret_cast<const float4*>(&ws[kk][tx * 4]);
#pragma unroll
            for (int r = 0; r < 8; r++) {
                float a = xs[kk][ty * 8 + r];
                acc[r][0] += a * b.x;
                acc[r][1] += a * b.y;
                acc[r][2] += a * b.z;
                acc[r][3] += a * b.w;
            }
        }
        __syncthreads();
    }
#pragma unroll
    for (int r = 0; r < 8; r++) {
        int row = row0 + ty * 8 + r;
        float4 v = make_float4(acc[r][0], acc[r][1], acc[r][2], acc[r][3]);
        *reinterpret_cast<float4*>(&g_h[row * C_OUT + tx * 4]) = v;
    }
}

// ---------------------------------------------------------------------
// Kernel 2: a_src[i] = h[i]·att_src, a_dst[i] = h[i]·att_dst
// one warp per row; lane covers 4 channels (float4)
// ---------------------------------------------------------------------
__global__ __launch_bounds__(256) void attn_scores_kernel(
    const float* __restrict__ att_src, const float* __restrict__ att_dst) {
    int warp = threadIdx.x >> 5;
    int lane = threadIdx.x & 31;
    int row  = blockIdx.x * 8 + warp;
    if (row >= N_NODES) return;

    float4 hv = *reinterpret_cast<const float4*>(&g_h[row * C_OUT + lane * 4]);
    float4 as = *reinterpret_cast<const float4*>(&att_src[lane * 4]);
    float4 ad = *reinterpret_cast<const float4*>(&att_dst[lane * 4]);
    float s = hv.x * as.x + hv.y * as.y + hv.z * as.z + hv.w * as.w;
    float d = hv.x * ad.x + hv.y * ad.y + hv.z * ad.z + hv.w * ad.w;
#pragma unroll
    for (int o = 16; o > 0; o >>= 1) {
        s += __shfl_xor_sync(0xFFFFFFFFu, s, o);
        d += __shfl_xor_sync(0xFFFFFFFFu, d, o);
    }
    if (lane == 0) { g_asrc[row] = s; g_adst[row] = d; }
}

// ---------------------------------------------------------------------
// Kernel 3: scan adj row-major once (256 MB, HBM-bound), build CSC lists.
// Skip the diagonal — the self loop is added unconditionally in kernel 4
// (reference SETS diag to 1, regardless of its original value).
// ---------------------------------------------------------------------
__global__ __launch_bounds__(256) void scan_adj_kernel(const float* __restrict__ adj) {
    const int total4 = (N_NODES / 4) * N_NODES;  // 16,777,216 float4s
    int stride = gridDim.x * blockDim.x;
    for (int q = blockIdx.x * blockDim.x + threadIdx.x; q < total4; q += stride) {
        float4 v = reinterpret_cast<const float4*>(adj)[q];
        if (v.x == 0.0f && v.y == 0.0f && v.z == 0.0f && v.w == 0.0f) continue;
        int base = q * 4;
        int i = base >> 13;          // row
        int j = base & (N_NODES - 1);
        float vals[4] = {v.x, v.y, v.z, v.w};
#pragma unroll
        for (int t = 0; t < 4; t++) {
            if (vals[t] != 0.0f) {
                int jj = j + t;
                if (jj != i) {
                    int pos = atomicAdd(&g_cnt[jj], 1);
                    if (pos < MAX_DEG) g_list[jj * MAX_DEG + pos] = i;
                }
            }
        }
    }
}

// ---------------------------------------------------------------------
// Kernel 4: per-column softmax-aggregate.
// out[j,c] = ( e_self*h[j,c] + Σ_d e_d * h[i_d,c] ) / colsum  + bias[c]
// h is 4 MB -> L2-resident; gathers are coalesced 512B rows.
// ---------------------------------------------------------------------
__global__ __launch_bounds__(128) void aggregate_kernel(
    const float* __restrict__ bias, float* __restrict__ out) {
    int j = blockIdx.x;
    int t = threadIdx.x;  // channel, 0..127

    __shared__ int   sidx[MAX_DEG];
    __shared__ float sew[MAX_DEG];

    int cnt = g_cnt[j];
    if (cnt > MAX_DEG) cnt = MAX_DEG;
    float adst_j = g_adst[j];

    if (t < cnt) {
        int i = g_list[j * MAX_DEG + t];
        sidx[t] = i;
        float z = g_asrc[i] + adst_j;
        z = (z > 0.0f) ? z : NEG_SLOPE * z;
        sew[t] = expf(z);
    }
    __syncthreads();

    // self-loop term (always present, weight exp(lrelu(a_src[j]+a_dst[j])))
    float zs = g_asrc[j] + adst_j;
    zs = (zs > 0.0f) ? zs : NEG_SLOPE * zs;
    float es  = expf(zs);
    float acc = es * g_h[j * C_OUT + t];
    float sum = es;

    int d = 0;
#pragma unroll 4
    for (; d < cnt; d++) {
        float e = sew[d];
        acc += e * g_h[sidx[d] * C_OUT + t];
        sum += e;
    }
    out[j * C_OUT + t] = acc / sum + bias[t];
}

// ---------------------------------------------------------------------
extern "C" void kernel_launch(void* const* d_in, const int* in_sizes, int n_in,
                              void* d_out, int out_size) {
    const float* x       = (const float*)d_in[0];
    const float* adj     = (const float*)d_in[1];
    const float* W       = (const float*)d_in[2];
    const float* att_src = (const float*)d_in[3];
    const float* att_dst = (const float*)d_in[4];
    const float* bias    = (const float*)d_in[5];
    float* out = (float*)d_out;

    zero_cnt_kernel<<<(N_NODES + 255) / 256, 256>>>();
    gemm_h_kernel<<<N_NODES / BM, 256>>>(x, W);
    attn_scores_kernel<<<N_NODES / 8, 256>>>(att_src, att_dst);
    scan_adj_kernel<<<2048, 256>>>(adj);
    aggregate_kernel<<<N_NODES, C_OUT>>>(bias, out);
}

// round 2
// speedup vs baseline: 1.1286x; 1.1286x over previous
#include <cuda_runtime.h>
#include <cuda_bf16.h>
#include <math.h>

#define N_NODES   8192
#define C_IN      256
#define C_OUT     128
#define NEG_SLOPE 0.2f
#define MAX_DEG   128

#define GEMM_BLOCKS 128          // 8192 / BM
#define SCAN_BLOCKS 2048
#define BM 64
#define BK 16

// -------- scratch (__device__ globals; zero-initialized at module load) ----
__device__ float g_h[N_NODES * C_OUT];      // 4 MB, h = x @ W
__device__ float g_asrc[N_NODES];
__device__ float g_adst[N_NODES];
__device__ int   g_cnt[N_NODES];            // per-column degree (excl. self)
__device__ int   g_list[N_NODES * MAX_DEG]; // 4 MB, CSC row lists

// ---------------------------------------------------------------------
// Fused front kernel: blocks [0, GEMM_BLOCKS) do the GEMM h = x@W with an
// attention-score epilogue; blocks [GEMM_BLOCKS, +SCAN_BLOCKS) stream adj
// once and build CSC neighbor lists. The two halves touch disjoint state,
// so they overlap (compute-bound GEMM under the memory-bound scan).
// g_cnt is zeroed by the PREVIOUS aggregate launch (and is zero-init on
// module load), so no reset race exists here.
// ---------------------------------------------------------------------
__global__ __launch_bounds__(256) void fused_front_kernel(
    const float* __restrict__ x, const float* __restrict__ W,
    const float* __restrict__ adj,
    const float* __restrict__ att_src, const float* __restrict__ att_dst) {

    if (blockIdx.x < GEMM_BLOCKS) {
        // ================= GEMM + attention epilogue =================
        __shared__ float xs[BK][BM];
        __shared__ float ws[BK][C_OUT];

        int tid  = threadIdx.x;
        int row0 = blockIdx.x * BM;
        int tx = tid & 31;   // channel group: c = tx*4
        int ty = tid >> 5;   // row group: r0 = ty*8  (warp == fixed ty)

        float acc[8][4];
#pragma unroll
        for (int r = 0; r < 8; r++)
#pragma unroll
            for (int c = 0; c < 4; c++) acc[r][c] = 0.0f;

        for (int k0 = 0; k0 < C_IN; k0 += BK) {
            {
                int r  = tid >> 2;
                int kk = (tid & 3) * 4;
                float4 v = *reinterpret_cast<const float4*>(
                    &x[(row0 + r) * C_IN + k0 + kk]);
                xs[kk + 0][r] = v.x; xs[kk + 1][r] = v.y;
                xs[kk + 2][r] = v.z; xs[kk + 3][r] = v.w;
            }
            {
                int kk = tid >> 5;
                int c  = (tid & 31) * 4;
                *reinterpret_cast<float4*>(&ws[kk][c]) =
                    *reinterpret_cast<const float4*>(&W[(k0 + kk) * C_OUT + c]);
                *reinterpret_cast<float4*>(&ws[kk + 8][c]) =
                    *reinterpret_cast<const float4*>(&W[(k0 + kk + 8) * C_OUT + c]);
            }
            __syncthreads();
#pragma unroll
            for (int kk = 0; kk < BK; kk++) {
                float4 b = *reinterpret_cast<const float4*>(&ws[kk][tx * 4]);
#pragma unroll
                for (int r = 0; r < 8; r++) {
                    float a = xs[kk][ty * 8 + r];
                    acc[r][0] += a * b.x;
                    acc[r][1] += a * b.y;
                    acc[r][2] += a * b.z;
                    acc[r][3] += a * b.w;
                }
            }
            __syncthreads();
        }

        float4 as = *reinterpret_cast<const float4*>(&att_src[tx * 4]);
        float4 ad = *reinterpret_cast<const float4*>(&att_dst[tx * 4]);

#pragma unroll
        for (int r = 0; r < 8; r++) {
            int row = row0 + ty * 8 + r;
            float4 v = make_float4(acc[r][0], acc[r][1], acc[r][2], acc[r][3]);
            *reinterpret_cast<float4*>(&g_h[row * C_OUT + tx * 4]) = v;

            // attention scores: warp-reduce across the 32 channel groups
            float s = v.x * as.x + v.y * as.y + v.z * as.z + v.w * as.w;
            float d = v.x * ad.x + v.y * ad.y + v.z * ad.z + v.w * ad.w;
#pragma unroll
            for (int o = 16; o > 0; o >>= 1) {
                s += __shfl_xor_sync(0xFFFFFFFFu, s, o);
                d += __shfl_xor_sync(0xFFFFFFFFu, d, o);
            }
            if (tx == 0) { g_asrc[row] = s; g_adst[row] = d; }
        }
    } else {
        // ================= adjacency scan (HBM-bound) =================
        // 16,777,216 uint4s / (2048*256 threads) = 32 per thread, unroll 4.
        const uint4* a4 = reinterpret_cast<const uint4*>(adj);
        int tid0   = (blockIdx.x - GEMM_BLOCKS) * 256 + threadIdx.x;
        const int stride = SCAN_BLOCKS * 256;           // 524288
        const int total4 = (N_NODES / 4) * N_NODES;     // 16777216

        for (int q = tid0; q < total4; q += 4 * stride) {
            int q0 = q, q1 = q + stride, q2 = q + 2 * stride, q3 = q + 3 * stride;
            uint4 v0 = __ldcs(&a4[q0]);
            uint4 v1 = __ldcs(&a4[q1]);
            uint4 v2 = __ldcs(&a4[q2]);
            uint4 v3 = __ldcs(&a4[q3]);

            uint4  vv[4] = {v0, v1, v2, v3};
            int    qq[4] = {q0, q1, q2, q3};
#pragma unroll
            for (int u = 0; u < 4; u++) {
                uint4 v = vv[u];
                if ((v.x | v.y | v.z | v.w) == 0u) continue;
                int qc = qq[u];
                int i  = qc >> 11;                 // row (2048 uint4 per row)
                int j0 = (qc & 2047) << 2;         // first column of the 4
                unsigned int b[4] = {v.x, v.y, v.z, v.w};
#pragma unroll
                for (int t = 0; t < 4; t++) {
                    if (b[t] != 0u) {
                        int jj = j0 + t;
                        if (jj != i) {             // diagonal handled in aggregate
                            int pos = atomicAdd(&g_cnt[jj], 1);
                            if (pos < MAX_DEG) g_list[jj * MAX_DEG + pos] = i;
                        }
                    }
                }
            }
        }
    }
}

// ---------------------------------------------------------------------
// Aggregate: per-column softmax + gather. Resets g_cnt for the next
// replay (device globals start zeroed, so the first run is consistent).
// ---------------------------------------------------------------------
__global__ __launch_bounds__(128) void aggregate_kernel(
    const float* __restrict__ bias, float* __restrict__ out) {
    int j = blockIdx.x;
    int t = threadIdx.x;  // channel, 0..127

    __shared__ int   sidx[MAX_DEG];
    __shared__ float sew[MAX_DEG];

    int cnt = g_cnt[j];
    if (cnt > MAX_DEG) cnt = MAX_DEG;
    float adst_j = g_adst[j];

    if (t < cnt) {
        int i = g_list[j * MAX_DEG + t];
        sidx[t] = i;
        float z = g_asrc[i] + adst_j;
        z = (z > 0.0f) ? z : NEG_SLOPE * z;
        sew[t] = __expf(z);
    }
    __syncthreads();
    if (t == 0) g_cnt[j] = 0;   // reset for next graph replay

    // self-loop term (reference SETS the diagonal to 1 -> always present)
    float zs = g_asrc[j] + adst_j;
    zs = (zs > 0.0f) ? zs : NEG_SLOPE * zs;
    float es  = __expf(zs);
    float acc = es * g_h[j * C_OUT + t];
    float sum = es;

#pragma unroll 4
    for (int d = 0; d < cnt; d++) {
        float e = sew[d];
        acc += e * g_h[sidx[d] * C_OUT + t];
        sum += e;
    }
    out[j * C_OUT + t] = acc / sum + bias[t];
}

// ---------------------------------------------------------------------
extern "C" void kernel_launch(void* const* d_in, const int* in_sizes, int n_in,
                              void* d_out, int out_size) {
    const float* x       = (const float*)d_in[0];
    const float* adj     = (const float*)d_in[1];
    const float* W       = (const float*)d_in[2];
    const float* att_src = (const float*)d_in[3];
    const float* att_dst = (const float*)d_in[4];
    const float* bias    = (const float*)d_in[5];
    float* out = (float*)d_out;

    fused_front_kernel<<<GEMM_BLOCKS + SCAN_BLOCKS, 256>>>(x, W, adj, att_src, att_dst);
    aggregate_kernel<<<N_NODES, C_OUT>>>(bias, out);
}